// round 1
// baseline (speedup 1.0000x reference)
#include <cuda_runtime.h>

// Fused: ConvTranspose3d(3->16, k=3, s=2, p=1, out_pad=1) + bias + MaxPool3d(2)
//        + softmax(ch) - subtract, swish, max(ch).
// Input  x: [4,3,64,64,64] f32, w: [3,16,3,3,3], b: [16], subtract: [16]
// Output: [4,64,64,64] f32
//
// Key identity: final voxel (n,d,h,w) depends only on x[n, :, d..d+1, h..h+1, w..w+1]
// (x[64] == 0 at high boundaries). Even conv position 2d uses tap kd=1 @ x[d];
// odd position 2d+1 uses kd=2 @ x[d] and kd=0 @ x[d+1]. Same per h, w.

#define N_BATCH 4
#define CIN 3
#define COUT 16
#define DIM 64
#define TILE_W 66   // x row tile: indices 0..64 valid (index 64 == zero pad), +1 pad

__global__ __launch_bounds__(128) void fused_ctmp_softswish_kernel(
    const float* __restrict__ x,
    const float* __restrict__ wgt,
    const float* __restrict__ bias_g,
    const float* __restrict__ sub_g,
    float* __restrict__ out)
{
    // per-warp x tile: [warp][cin*4 + dd*2 + hh][wpos]
    __shared__ float tile[4][12][TILE_W];

    const int lane = threadIdx.x & 31;
    const int wid  = threadIdx.x >> 5;
    const int c    = lane & 15;   // channel owned by this lane
    const int half = lane >> 4;   // which of the 2 adjacent-w voxels

    // ---- weights for channel c into registers (81 floats), once per warp ----
    float wr[81];
    #pragma unroll
    for (int cin = 0; cin < CIN; ++cin) {
        #pragma unroll
        for (int k = 0; k < 27; ++k) {
            wr[cin * 27 + k] = __ldg(&wgt[(cin * COUT + c) * 27 + k]);
        }
    }
    const float bias = __ldg(&bias_g[c]);
    const float subc = __ldg(&sub_g[c]);

    // tap tables: parity 0 (even conv pos): k=1 @ x offset 0
    //             parity 1 (odd  conv pos): k=2 @ off 0, k=0 @ off 1
    const int NP[2]      = {1, 2};
    const int KTAP[2][2] = {{1, 0}, {2, 0}};
    const int XOFF[2][2] = {{0, 0}, {0, 1}};

    const int gwarp  = blockIdx.x * 4 + wid;
    const int nwarps = gridDim.x * 4;
    const int nrows  = N_BATCH * DIM * DIM;   // 16384 (n,d,h) rows

    for (int row = gwarp; row < nrows; row += nwarps) {
        const int h = row & 63;
        const int d = (row >> 6) & 63;
        const int n = row >> 12;

        // ---- cooperative per-warp x tile load ----
        #pragma unroll
        for (int comb = 0; comb < 12; ++comb) {
            const int cin = comb >> 2;
            const int dd  = (comb >> 1) & 1;
            const int hh  = comb & 1;
            const int dcur = d + dd;
            const int hcur = h + hh;
            const bool rowok = (dcur < DIM) && (hcur < DIM);
            const float* src = x + (((n * CIN + cin) * DIM + dcur) * DIM + hcur) * DIM;
            for (int wp = lane; wp < TILE_W; wp += 32) {
                float v = 0.f;
                if (rowok && wp < DIM) v = __ldg(&src[wp]);
                tile[wid][comb][wp] = v;
            }
        }
        __syncwarp();

        const float* tw = &tile[wid][0][0];

        for (int w0 = 0; w0 < DIM; w0 += 2) {
            const int wv = w0 + half;   // this lane's voxel w

            // load the 24 x values for this voxel (broadcast within each half)
            float xv[12][2];
            #pragma unroll
            for (int comb = 0; comb < 12; ++comb) {
                xv[comb][0] = tw[comb * TILE_W + wv];
                xv[comb][1] = tw[comb * TILE_W + wv + 1];
            }

            // 8 pooled conv-output candidates (one per parity combo)
            float acc[8];
            #pragma unroll
            for (int i = 0; i < 8; ++i) acc[i] = 0.f;

            #pragma unroll
            for (int cin = 0; cin < CIN; ++cin) {
                #pragma unroll
                for (int pd = 0; pd < 2; ++pd) {
                    #pragma unroll
                    for (int jd = 0; jd < 2; ++jd) {
                        if (jd >= NP[pd]) continue;
                        const int kd = KTAP[pd][jd], dd = XOFF[pd][jd];
                        #pragma unroll
                        for (int ph = 0; ph < 2; ++ph) {
                            #pragma unroll
                            for (int jh = 0; jh < 2; ++jh) {
                                if (jh >= NP[ph]) continue;
                                const int kh = KTAP[ph][jh], hh = XOFF[ph][jh];
                                const int comb = cin * 4 + dd * 2 + hh;
                                #pragma unroll
                                for (int pw = 0; pw < 2; ++pw) {
                                    #pragma unroll
                                    for (int jw = 0; jw < 2; ++jw) {
                                        if (jw >= NP[pw]) continue;
                                        const int kw = KTAP[pw][jw], ww = XOFF[pw][jw];
                                        const float wv_ = wr[cin * 27 + kd * 9 + kh * 3 + kw];
                                        acc[pd * 4 + ph * 2 + pw] =
                                            fmaf(wv_, xv[comb][ww], acc[pd * 4 + ph * 2 + pw]);
                                    }
                                }
                            }
                        }
                    }
                }
            }

            // maxpool over the 8 candidates, add bias
            float m = acc[0];
            #pragma unroll
            for (int i = 1; i < 8; ++i) m = fmaxf(m, acc[i]);
            m += bias;

            // softmax across the 16 channel-lanes (masks 1/2/4/8 keep halves separate)
            float mx = m;
            #pragma unroll
            for (int s = 1; s < 16; s <<= 1)
                mx = fmaxf(mx, __shfl_xor_sync(0xffffffffu, mx, s));
            const float e = __expf(m - mx);
            float sum = e;
            #pragma unroll
            for (int s = 1; s < 16; s <<= 1)
                sum += __shfl_xor_sync(0xffffffffu, sum, s);
            const float sft = __fdividef(e, sum);

            // subtract + swish
            const float z  = sft - subc;
            const float sw = __fdividef(z, 1.f + __expf(-z));

            // max over channels
            float r = sw;
            #pragma unroll
            for (int s = 1; s < 16; s <<= 1)
                r = fmaxf(r, __shfl_xor_sync(0xffffffffu, r, s));

            if (c == 0)
                out[((n * DIM + d) * DIM + h) * DIM + wv] = r;
        }
        __syncwarp();   // tile reuse barrier before next row
    }
}

extern "C" void kernel_launch(void* const* d_in, const int* in_sizes, int n_in,
                              void* d_out, int out_size) {
    const float* x   = (const float*)d_in[0];
    const float* w   = (const float*)d_in[1];
    const float* b   = (const float*)d_in[2];
    const float* sub = (const float*)d_in[3];
    float* out = (float*)d_out;
    (void)in_sizes; (void)n_in; (void)out_size;
    fused_ctmp_softswish_kernel<<<2048, 128>>>(x, w, b, sub, out);
}

// round 2
// speedup vs baseline: 1.3535x; 1.3535x over previous
#include <cuda_runtime.h>

// Fused: ConvTranspose3d(3->16, k=3, s=2, p=1, out_pad=1) + bias + MaxPool3d(2)
//        + softmax(ch) - subtract, swish, max(ch).
// Input  x: [4,3,64,64,64] f32, w: [3,16,3,3,3], b: [16], subtract: [16]
// Output: [4,64,64,64] f32
//
// Final voxel (n,d,h,w) depends only on x[n, :, d..d+1, h..h+1, w..w+1].
// Lane c=lane&15 owns channel c; half=lane>>4 picks one of 2 adjacent-w voxels.
// R2: batch 4 voxel-pairs per iteration and interleave the three shuffle-
// reduction chains across the batch (ILP=4) to hide SHFL latency.

#define N_BATCH 4
#define CIN 3
#define COUT 16
#define DIM 64
#define TILE_W 66
#define JB 4   // voxel-pairs per batch

__global__ __launch_bounds__(128) void fused_ctmp_softswish_kernel(
    const float* __restrict__ x,
    const float* __restrict__ wgt,
    const float* __restrict__ bias_g,
    const float* __restrict__ sub_g,
    float* __restrict__ out)
{
    __shared__ float tile[4][12][TILE_W];

    const int lane = threadIdx.x & 31;
    const int wid  = threadIdx.x >> 5;
    const int c    = lane & 15;
    const int half = lane >> 4;

    // weights for channel c (81 floats) in registers
    float wr[81];
    #pragma unroll
    for (int cin = 0; cin < CIN; ++cin) {
        #pragma unroll
        for (int k = 0; k < 27; ++k)
            wr[cin * 27 + k] = __ldg(&wgt[(cin * COUT + c) * 27 + k]);
    }
    const float bias = __ldg(&bias_g[c]);
    const float subc = __ldg(&sub_g[c]);

    // parity tap tables: even conv pos -> k=1 @ off 0; odd -> k=2 @ off 0, k=0 @ off 1
    const int NP[2]      = {1, 2};
    const int KTAP[2][2] = {{1, 0}, {2, 0}};
    const int XOFF[2][2] = {{0, 0}, {0, 1}};

    const int gwarp  = blockIdx.x * 4 + wid;
    const int nwarps = gridDim.x * 4;
    const int nrows  = N_BATCH * DIM * DIM;

    for (int row = gwarp; row < nrows; row += nwarps) {
        const int h = row & 63;
        const int d = (row >> 6) & 63;
        const int n = row >> 12;

        // cooperative per-warp tile load: [cin*4 + dd*2 + hh][wpos]
        #pragma unroll
        for (int comb = 0; comb < 12; ++comb) {
            const int cin = comb >> 2;
            const int dd  = (comb >> 1) & 1;
            const int hh  = comb & 1;
            const int dcur = d + dd;
            const int hcur = h + hh;
            const bool rowok = (dcur < DIM) && (hcur < DIM);
            const float* src = x + (((n * CIN + cin) * DIM + dcur) * DIM + hcur) * DIM;
            for (int wp = lane; wp < TILE_W; wp += 32) {
                float v = 0.f;
                if (rowok && wp < DIM) v = __ldg(&src[wp]);
                tile[wid][comb][wp] = v;
            }
        }
        __syncwarp();

        const float* tw = &tile[wid][0][0];
        float* orow = out + ((n * DIM + d) * DIM + h) * DIM;

        for (int w0 = 0; w0 < DIM; w0 += 2 * JB) {
            float m[JB];

            // ---- compute phase: 4 independent voxel-pairs, acc reused per j ----
            #pragma unroll
            for (int j = 0; j < JB; ++j) {
                const int wv = w0 + 2 * j + half;

                float acc[8];
                #pragma unroll
                for (int i = 0; i < 8; ++i) acc[i] = 0.f;

                #pragma unroll
                for (int cin = 0; cin < CIN; ++cin) {
                    #pragma unroll
                    for (int dd = 0; dd < 2; ++dd) {
                        #pragma unroll
                        for (int hh = 0; hh < 2; ++hh) {
                            const int comb = cin * 4 + dd * 2 + hh;
                            const float x0 = tw[comb * TILE_W + wv];
                            const float x1 = tw[comb * TILE_W + wv + 1];
                            const float xx[2] = {x0, x1};
                            #pragma unroll
                            for (int pd = 0; pd < 2; ++pd) {
                                #pragma unroll
                                for (int jd = 0; jd < 2; ++jd) {
                                    if (jd >= NP[pd] || XOFF[pd][jd] != dd) continue;
                                    const int kd = KTAP[pd][jd];
                                    #pragma unroll
                                    for (int ph = 0; ph < 2; ++ph) {
                                        #pragma unroll
                                        for (int jh = 0; jh < 2; ++jh) {
                                            if (jh >= NP[ph] || XOFF[ph][jh] != hh) continue;
                                            const int kh = KTAP[ph][jh];
                                            #pragma unroll
                                            for (int pw = 0; pw < 2; ++pw) {
                                                #pragma unroll
                                                for (int jw = 0; jw < 2; ++jw) {
                                                    if (jw >= NP[pw]) continue;
                                                    const int kw = KTAP[pw][jw];
                                                    const float wv_ = wr[cin * 27 + kd * 9 + kh * 3 + kw];
                                                    acc[pd * 4 + ph * 2 + pw] =
                                                        fmaf(wv_, xx[XOFF[pw][jw]], acc[pd * 4 + ph * 2 + pw]);
                                                }
                                            }
                                        }
                                    }
                                }
                            }
                        }
                    }
                }

                float mm = acc[0];
                #pragma unroll
                for (int i = 1; i < 8; ++i) mm = fmaxf(mm, acc[i]);
                m[j] = mm + bias;
            }

            // ---- reduction phase: chains interleaved across the 4 pairs ----
            float mx[JB];
            #pragma unroll
            for (int j = 0; j < JB; ++j) mx[j] = m[j];
            #pragma unroll
            for (int s = 1; s < 16; s <<= 1) {
                #pragma unroll
                for (int j = 0; j < JB; ++j)
                    mx[j] = fmaxf(mx[j], __shfl_xor_sync(0xffffffffu, mx[j], s));
            }

            float e[JB], sum[JB];
            #pragma unroll
            for (int j = 0; j < JB; ++j) {
                e[j] = __expf(m[j] - mx[j]);
                sum[j] = e[j];
            }
            #pragma unroll
            for (int s = 1; s < 16; s <<= 1) {
                #pragma unroll
                for (int j = 0; j < JB; ++j)
                    sum[j] += __shfl_xor_sync(0xffffffffu, sum[j], s);
            }

            float r[JB];
            #pragma unroll
            for (int j = 0; j < JB; ++j) {
                const float sft = __fdividef(e[j], sum[j]);
                const float z   = sft - subc;
                r[j] = __fdividef(z, 1.f + __expf(-z));   // swish
            }
            #pragma unroll
            for (int s = 1; s < 16; s <<= 1) {
                #pragma unroll
                for (int j = 0; j < JB; ++j)
                    r[j] = fmaxf(r[j], __shfl_xor_sync(0xffffffffu, r[j], s));
            }

            if (c == 0) {
                #pragma unroll
                for (int j = 0; j < JB; ++j)
                    orow[w0 + 2 * j + half] = r[j];
            }
        }
        __syncwarp();
    }
}

extern "C" void kernel_launch(void* const* d_in, const int* in_sizes, int n_in,
                              void* d_out, int out_size) {
    const float* x   = (const float*)d_in[0];
    const float* w   = (const float*)d_in[1];
    const float* b   = (const float*)d_in[2];
    const float* sub = (const float*)d_in[3];
    float* out = (float*)d_out;
    (void)in_sizes; (void)n_in; (void)out_size;
    fused_ctmp_softswish_kernel<<<2048, 128>>>(x, w, b, sub, out);
}